// round 9
// baseline (speedup 1.0000x reference)
#include <cuda_runtime.h>
#include <cuda_fp16.h>
#include <cstdint>

// LightGCN: out = 0.25*(X + h1 + h2 + h3), h_{k+1} = A h_k
// R9: ONE persistent kernel. Phases separated by software grid barriers
// (sense-reversing; even count -> state self-restores each graph replay).
// Pull-based CSR, fp16 gathers/intermediates, fp32 accumulation.

#define N_NODES 100000
#define D_FEAT  64
#define MAX_E   1600000
#define MAXB    1184     // >= max co-resident blocks (148 SMs x 8)

// Static scratch (no allocation allowed). deg self-restores (reset in P2b).
__device__ __half g_hX[(size_t)N_NODES * D_FEAT];
__device__ __half g_h1[(size_t)N_NODES * D_FEAT];
__device__ __half g_h2[(size_t)N_NODES * D_FEAT];
__device__ int    g_deg[N_NODES];
__device__ int    g_off[N_NODES + 1];
__device__ int    g_rank[MAX_E];
__device__ int2   g_sedge[MAX_E];
__device__ int    g_psum[MAXB];
__device__ int    g_bar_count;          // returns to 0 after each barrier
__device__ volatile int g_bar_sense;    // even #barriers/call -> ends at 0

// Sense-reversing grid barrier. Deadlock-free iff all blocks co-resident
// (guaranteed: grid is clamped to occupancy_max * SM count on the host).
__device__ __forceinline__ void grid_barrier(int nblocks, int& sense) {
    __syncthreads();
    if (threadIdx.x == 0) {
        sense ^= 1;
        __threadfence();
        if (atomicAdd(&g_bar_count, 1) == nblocks - 1) {
            g_bar_count = 0;
            __threadfence();
            g_bar_sense = sense;
        } else {
            while (g_bar_sense != sense) __nanosleep(64);
        }
        __threadfence();
    }
    __syncthreads();
}

// Warp-cooperative node reduce: lanes 0-15 even edges, 16-31 odd edges;
// lane c owns features [4c,4c+4) (16 lanes x 8B = full 128B fp16 row).
__device__ __forceinline__ float4 warp_node_reduce_h(const __half* __restrict__ Hin,
                                                     int node, int c, int half) {
    int begin = g_off[node], end = g_off[node + 1];
    float4 acc = make_float4(0.f, 0.f, 0.f, 0.f);
    for (int e = begin + half; e < end; e += 2) {
        int2  p = g_sedge[e];
        float w = __int_as_float(p.y);
        uint2 u = reinterpret_cast<const uint2*>(Hin + (size_t)p.x * D_FEAT)[c];
        float2 fa = __half22float2(*reinterpret_cast<__half2*>(&u.x));
        float2 fb = __half22float2(*reinterpret_cast<__half2*>(&u.y));
        acc.x += w * fa.x; acc.y += w * fa.y; acc.z += w * fb.x; acc.w += w * fb.y;
    }
    acc.x += __shfl_xor_sync(0xffffffff, acc.x, 16);
    acc.y += __shfl_xor_sync(0xffffffff, acc.y, 16);
    acc.z += __shfl_xor_sync(0xffffffff, acc.z, 16);
    acc.w += __shfl_xor_sync(0xffffffff, acc.w, 16);
    return acc;
}

__global__ void __launch_bounds__(256, 4)
lightgcn_mega(const float* __restrict__ X,
              const int* __restrict__ src,
              const int* __restrict__ dst,
              const float* __restrict__ ew,
              float* __restrict__ out,
              int nE, int nblocks) {
    __shared__ int sh[256];
    int sense = 0;
    const int tid = blockIdx.x * 256 + threadIdx.x;
    const int nthreads = nblocks * 256;

    // ---- P1: X -> fp16, fused with dst histogram; atomic return = edge rank ----
    const int n8 = N_NODES * D_FEAT / 8;
    for (int i = tid; i < n8; i += nthreads) {
        const float4* x4 = reinterpret_cast<const float4*>(X);
        float4 a = x4[2 * i];
        float4 b = x4[2 * i + 1];
        __half2 h0 = __floats2half2_rn(a.x, a.y);
        __half2 h1 = __floats2half2_rn(a.z, a.w);
        __half2 h2 = __floats2half2_rn(b.x, b.y);
        __half2 h3 = __floats2half2_rn(b.z, b.w);
        uint4 r;
        r.x = *reinterpret_cast<unsigned*>(&h0);
        r.y = *reinterpret_cast<unsigned*>(&h1);
        r.z = *reinterpret_cast<unsigned*>(&h2);
        r.w = *reinterpret_cast<unsigned*>(&h3);
        reinterpret_cast<uint4*>(g_hX)[i] = r;
    }
    for (int e = tid; e < nE; e += nthreads)
        g_rank[e] = atomicAdd(&g_deg[dst[e]], 1);
    grid_barrier(nblocks, sense);                                    // B1

    // ---- P2a: per-chunk degree sums ----
    const int C = (N_NODES + nblocks - 1) / nblocks;   // nodes per block chunk
    const int lo = blockIdx.x * C;
    const int hi = (lo + C < N_NODES) ? lo + C : N_NODES;
    {
        int s = 0;
        for (int i = lo + threadIdx.x; i < hi; i += 256) s += g_deg[i];
        sh[threadIdx.x] = s;
        __syncthreads();
        for (int o = 128; o; o >>= 1) {
            if (threadIdx.x < o) sh[threadIdx.x] += sh[threadIdx.x + o];
            __syncthreads();
        }
        if (threadIdx.x == 0) g_psum[blockIdx.x] = sh[0];
        __syncthreads();
    }
    grid_barrier(nblocks, sense);                                    // B2

    // ---- P2b: chunk base + in-chunk scan -> off; reset deg ----
    {
        int s = 0;
        for (int j = threadIdx.x; j < blockIdx.x; j += 256) s += g_psum[j];
        sh[threadIdx.x] = s;
        __syncthreads();
        for (int o = 128; o; o >>= 1) {
            if (threadIdx.x < o) sh[threadIdx.x] += sh[threadIdx.x + o];
            __syncthreads();
        }
        int run = sh[0];
        __syncthreads();
        for (int start = lo; start < hi; start += 256) {
            int i = start + threadIdx.x;
            int v = (i < hi) ? g_deg[i] : 0;
            sh[threadIdx.x] = v;
            __syncthreads();
            for (int d = 1; d < 256; d <<= 1) {
                int x = (threadIdx.x >= d) ? sh[threadIdx.x - d] : 0;
                __syncthreads();
                sh[threadIdx.x] += x;
                __syncthreads();
            }
            int incl = sh[threadIdx.x];
            if (i < hi) {
                g_off[i] = run + incl - v;
                g_deg[i] = 0;              // self-restore for next replay
            }
            int tot = sh[255];
            __syncthreads();
            run += tot;
        }
        if (tid == 0) g_off[N_NODES] = nE;
    }
    grid_barrier(nblocks, sense);                                    // B3

    // ---- P3: atomic-free scatter ----
    for (int e = tid; e < nE; e += nthreads) {
        int pos = g_off[dst[e]] + g_rank[e];
        g_sedge[pos] = make_int2(src[e], __float_as_int(ew[e]));
    }
    grid_barrier(nblocks, sense);                                    // B4

    // ---- P4/P5/P6: pull layers (persistent warp-per-node) ----
    const int warp_id = tid >> 5;
    const int total_warps = nthreads >> 5;
    const int lane = threadIdx.x & 31;
    const int halfw = lane >> 4;
    const int c = lane & 15;

    // h1 = A * X
    for (int node = warp_id; node < N_NODES; node += total_warps) {
        float4 acc = warp_node_reduce_h(g_hX, node, c, halfw);
        if (halfw == 0) {
            __half2 h0 = __floats2half2_rn(acc.x, acc.y);
            __half2 h1 = __floats2half2_rn(acc.z, acc.w);
            uint2 u;
            u.x = *reinterpret_cast<unsigned*>(&h0);
            u.y = *reinterpret_cast<unsigned*>(&h1);
            reinterpret_cast<uint2*>(g_h1 + (size_t)node * D_FEAT)[c] = u;
        }
    }
    grid_barrier(nblocks, sense);                                    // B5

    // h2 = A * h1
    for (int node = warp_id; node < N_NODES; node += total_warps) {
        float4 acc = warp_node_reduce_h(g_h1, node, c, halfw);
        if (halfw == 0) {
            __half2 h0 = __floats2half2_rn(acc.x, acc.y);
            __half2 h1 = __floats2half2_rn(acc.z, acc.w);
            uint2 u;
            u.x = *reinterpret_cast<unsigned*>(&h0);
            u.y = *reinterpret_cast<unsigned*>(&h1);
            reinterpret_cast<uint2*>(g_h2 + (size_t)node * D_FEAT)[c] = u;
        }
    }
    grid_barrier(nblocks, sense);                                    // B6

    // h3 = A * h2, fused mean: out = 0.25*(X + h1 + h2 + h3)
    for (int node = warp_id; node < N_NODES; node += total_warps) {
        float4 acc = warp_node_reduce_h(g_h2, node, c, halfw);
        if (halfw == 0) {
            size_t idx = (size_t)node * D_FEAT + (c << 2);
            float4 x0 = *reinterpret_cast<const float4*>(X + idx);
            uint2 u1 = reinterpret_cast<const uint2*>(g_h1 + (size_t)node * D_FEAT)[c];
            uint2 u2 = reinterpret_cast<const uint2*>(g_h2 + (size_t)node * D_FEAT)[c];
            float2 a1 = __half22float2(*reinterpret_cast<__half2*>(&u1.x));
            float2 b1 = __half22float2(*reinterpret_cast<__half2*>(&u1.y));
            float2 a2 = __half22float2(*reinterpret_cast<__half2*>(&u2.x));
            float2 b2 = __half22float2(*reinterpret_cast<__half2*>(&u2.y));
            float4 o;
            o.x = 0.25f * (x0.x + a1.x + a2.x + acc.x);
            o.y = 0.25f * (x0.y + a1.y + a2.y + acc.y);
            o.z = 0.25f * (x0.z + b1.x + b2.x + acc.z);
            o.w = 0.25f * (x0.w + b1.y + b2.y + acc.w);
            *reinterpret_cast<float4*>(out + idx) = o;
        }
    }
    // 6 barriers total (even) -> g_bar_sense back to 0 for the next replay.
}

extern "C" void kernel_launch(void* const* d_in, const int* in_sizes, int n_in,
                              void* d_out, int out_size) {
    const float* X   = (const float*)d_in[0];
    const int*   src = (const int*)  d_in[1];
    const int*   dst = (const int*)  d_in[2];
    const float* ew  = (const float*)d_in[3];
    float* out = (float*)d_out;
    const int nE = in_sizes[1];

    // Clamp grid to guaranteed co-residency (required for the grid barrier).
    int dev = 0;
    cudaGetDevice(&dev);
    int sms = 0;
    cudaDeviceGetAttribute(&sms, cudaDevAttrMultiProcessorCount, dev);
    int perSm = 0;
    cudaOccupancyMaxActiveBlocksPerMultiprocessor(&perSm, lightgcn_mega, 256, 0);
    if (perSm < 1) perSm = 1;
    int nblocks = sms * perSm;
    if (nblocks > MAXB) nblocks = MAXB;

    lightgcn_mega<<<nblocks, 256>>>(X, src, dst, ew, out, nE, nblocks);
}

// round 10
// speedup vs baseline: 1.0984x; 1.0984x over previous
#include <cuda_runtime.h>
#include <cuda_fp16.h>
#include <cstdint>

// LightGCN: out = 0.25*(X + h1 + h2 + h3), h_{k+1} = A h_k
// R10 hybrid: CSR build = ONE persistent cooperative kernel (4 grid barriers,
// even -> self-restoring state). Pull layers stay as 3 separate high-occupancy
// kernels (R8 form: fp16 gathers/intermediates, fp32 accumulation).

#define N_NODES 100000
#define D_FEAT  64
#define MAX_E   1600000
#define MAXB    2368     // >= max co-resident blocks

// Static scratch (no allocation allowed). deg self-restores (reset in P2b).
__device__ __half g_hX[(size_t)N_NODES * D_FEAT];
__device__ __half g_h1[(size_t)N_NODES * D_FEAT];
__device__ __half g_h2[(size_t)N_NODES * D_FEAT];
__device__ int    g_deg[N_NODES];
__device__ int    g_off[N_NODES + 1];
__device__ int    g_rank[MAX_E];
__device__ int2   g_sedge[MAX_E];
__device__ int    g_psum[MAXB];
__device__ int    g_bar_count;          // returns to 0 after each barrier
__device__ volatile int g_bar_sense;    // 4 barriers/call -> ends at 0

// Sense-reversing grid barrier (all blocks co-resident by construction).
__device__ __forceinline__ void grid_barrier(int nblocks, int& sense) {
    __syncthreads();
    if (threadIdx.x == 0) {
        sense ^= 1;
        __threadfence();
        if (atomicAdd(&g_bar_count, 1) == nblocks - 1) {
            g_bar_count = 0;
            __threadfence();
            g_bar_sense = sense;
        } else {
            while (g_bar_sense != sense) __nanosleep(64);
        }
        __threadfence();
    }
    __syncthreads();
}

// ---- build: x2h + hist/rank | chunk sums | scan->off (+deg reset) | scatter ----
__global__ void __launch_bounds__(256)
k_build(const float* __restrict__ X,
        const int* __restrict__ src,
        const int* __restrict__ dst,
        const float* __restrict__ ew,
        int nE, int nblocks) {
    __shared__ int sh[256];
    int sense = 0;
    const int tid = blockIdx.x * 256 + threadIdx.x;
    const int nthreads = nblocks * 256;

    // P1: X -> fp16; dst histogram, atomic return = within-dst edge rank.
    const int n8 = N_NODES * D_FEAT / 8;
    for (int i = tid; i < n8; i += nthreads) {
        const float4* x4 = reinterpret_cast<const float4*>(X);
        float4 a = x4[2 * i];
        float4 b = x4[2 * i + 1];
        __half2 h0 = __floats2half2_rn(a.x, a.y);
        __half2 h1 = __floats2half2_rn(a.z, a.w);
        __half2 h2 = __floats2half2_rn(b.x, b.y);
        __half2 h3 = __floats2half2_rn(b.z, b.w);
        uint4 r;
        r.x = *reinterpret_cast<unsigned*>(&h0);
        r.y = *reinterpret_cast<unsigned*>(&h1);
        r.z = *reinterpret_cast<unsigned*>(&h2);
        r.w = *reinterpret_cast<unsigned*>(&h3);
        reinterpret_cast<uint4*>(g_hX)[i] = r;
    }
    for (int e = tid; e < nE; e += nthreads)
        g_rank[e] = atomicAdd(&g_deg[dst[e]], 1);
    grid_barrier(nblocks, sense);                                    // B1

    // P2a: per-chunk degree sums.
    const int C = (N_NODES + nblocks - 1) / nblocks;
    const int lo = blockIdx.x * C;
    const int hi = (lo + C < N_NODES) ? lo + C : N_NODES;
    {
        int s = 0;
        for (int i = lo + threadIdx.x; i < hi; i += 256) s += g_deg[i];
        sh[threadIdx.x] = s;
        __syncthreads();
        for (int o = 128; o; o >>= 1) {
            if (threadIdx.x < o) sh[threadIdx.x] += sh[threadIdx.x + o];
            __syncthreads();
        }
        if (threadIdx.x == 0) g_psum[blockIdx.x] = sh[0];
        __syncthreads();
    }
    grid_barrier(nblocks, sense);                                    // B2

    // P2b: chunk base + in-chunk exclusive scan -> off; reset deg.
    {
        int s = 0;
        for (int j = threadIdx.x; j < blockIdx.x; j += 256) s += g_psum[j];
        sh[threadIdx.x] = s;
        __syncthreads();
        for (int o = 128; o; o >>= 1) {
            if (threadIdx.x < o) sh[threadIdx.x] += sh[threadIdx.x + o];
            __syncthreads();
        }
        int run = sh[0];
        __syncthreads();
        for (int start = lo; start < hi; start += 256) {
            int i = start + threadIdx.x;
            int v = (i < hi) ? g_deg[i] : 0;
            sh[threadIdx.x] = v;
            __syncthreads();
            for (int d = 1; d < 256; d <<= 1) {
                int x = (threadIdx.x >= d) ? sh[threadIdx.x - d] : 0;
                __syncthreads();
                sh[threadIdx.x] += x;
                __syncthreads();
            }
            int incl = sh[threadIdx.x];
            if (i < hi) {
                g_off[i] = run + incl - v;
                g_deg[i] = 0;              // self-restore for next replay
            }
            int tot = sh[255];
            __syncthreads();
            run += tot;
        }
        if (tid == 0) g_off[N_NODES] = nE;
    }
    grid_barrier(nblocks, sense);                                    // B3

    // P3: atomic-free scatter.
    for (int e = tid; e < nE; e += nthreads) {
        int pos = g_off[dst[e]] + g_rank[e];
        g_sedge[pos] = make_int2(src[e], __float_as_int(ew[e]));
    }
    grid_barrier(nblocks, sense);                                    // B4 (parity)
}

// ---------------- Pull SpMM (R8 form) ----------------
__device__ __forceinline__ float4 warp_node_reduce_h(const __half* __restrict__ Hin,
                                                     int node, int c, int half) {
    int begin = g_off[node], end = g_off[node + 1];
    float4 acc = make_float4(0.f, 0.f, 0.f, 0.f);
    for (int e = begin + half; e < end; e += 2) {
        int2  p = g_sedge[e];
        float w = __int_as_float(p.y);
        uint2 u = reinterpret_cast<const uint2*>(Hin + (size_t)p.x * D_FEAT)[c];
        float2 fa = __half22float2(*reinterpret_cast<__half2*>(&u.x));
        float2 fb = __half22float2(*reinterpret_cast<__half2*>(&u.y));
        acc.x += w * fa.x; acc.y += w * fa.y; acc.z += w * fb.x; acc.w += w * fb.y;
    }
    acc.x += __shfl_xor_sync(0xffffffff, acc.x, 16);
    acc.y += __shfl_xor_sync(0xffffffff, acc.y, 16);
    acc.z += __shfl_xor_sync(0xffffffff, acc.z, 16);
    acc.w += __shfl_xor_sync(0xffffffff, acc.w, 16);
    return acc;
}

__global__ void k_pull_h(const __half* __restrict__ Hin,
                         __half* __restrict__ Hout) {
    int gwarp = (blockIdx.x * blockDim.x + threadIdx.x) >> 5;
    if (gwarp >= N_NODES) return;
    int lane = threadIdx.x & 31;
    int half = lane >> 4;
    int c    = lane & 15;
    float4 acc = warp_node_reduce_h(Hin, gwarp, c, half);
    if (half == 0) {
        __half2 h0 = __floats2half2_rn(acc.x, acc.y);
        __half2 h1 = __floats2half2_rn(acc.z, acc.w);
        uint2 u;
        u.x = *reinterpret_cast<unsigned*>(&h0);
        u.y = *reinterpret_cast<unsigned*>(&h1);
        reinterpret_cast<uint2*>(Hout + (size_t)gwarp * D_FEAT)[c] = u;
    }
}

__global__ void k_pull_final_h(const __half* __restrict__ Hin,   // h2 (fp16)
                               const float* __restrict__ X,
                               const __half* __restrict__ H1,
                               float* __restrict__ out) {
    int gwarp = (blockIdx.x * blockDim.x + threadIdx.x) >> 5;
    if (gwarp >= N_NODES) return;
    int lane = threadIdx.x & 31;
    int half = lane >> 4;
    int c    = lane & 15;
    float4 acc = warp_node_reduce_h(Hin, gwarp, c, half);   // h3 chunk
    if (half == 0) {
        size_t idx = (size_t)gwarp * D_FEAT + (c << 2);
        float4 x0 = *reinterpret_cast<const float4*>(X + idx);
        uint2 u1 = reinterpret_cast<const uint2*>(H1  + (size_t)gwarp * D_FEAT)[c];
        uint2 u2 = reinterpret_cast<const uint2*>(Hin + (size_t)gwarp * D_FEAT)[c];
        float2 a1 = __half22float2(*reinterpret_cast<__half2*>(&u1.x));
        float2 b1 = __half22float2(*reinterpret_cast<__half2*>(&u1.y));
        float2 a2 = __half22float2(*reinterpret_cast<__half2*>(&u2.x));
        float2 b2 = __half22float2(*reinterpret_cast<__half2*>(&u2.y));
        float4 o;
        o.x = 0.25f * (x0.x + a1.x + a2.x + acc.x);
        o.y = 0.25f * (x0.y + a1.y + a2.y + acc.y);
        o.z = 0.25f * (x0.z + b1.x + b2.x + acc.z);
        o.w = 0.25f * (x0.w + b1.y + b2.y + acc.w);
        *reinterpret_cast<float4*>(out + idx) = o;
    }
}

extern "C" void kernel_launch(void* const* d_in, const int* in_sizes, int n_in,
                              void* d_out, int out_size) {
    const float* X   = (const float*)d_in[0];
    const int*   src = (const int*)  d_in[1];
    const int*   dst = (const int*)  d_in[2];
    const float* ew  = (const float*)d_in[3];
    float* out = (float*)d_out;
    const int nE = in_sizes[1];

    __half* hX = nullptr;
    __half* h1 = nullptr;
    __half* h2 = nullptr;
    cudaGetSymbolAddress((void**)&hX, g_hX);
    cudaGetSymbolAddress((void**)&h1, g_h1);
    cudaGetSymbolAddress((void**)&h2, g_h2);

    // Co-residency clamp for the build kernel's grid barrier.
    int dev = 0;
    cudaGetDevice(&dev);
    int sms = 0;
    cudaDeviceGetAttribute(&sms, cudaDevAttrMultiProcessorCount, dev);
    int perSm = 0;
    cudaOccupancyMaxActiveBlocksPerMultiprocessor(&perSm, k_build, 256, 0);
    if (perSm < 1) perSm = 1;
    int nb = sms * perSm;
    if (nb > MAXB) nb = MAXB;

    const int TB = 256;
    const int gridPull = (N_NODES * 32 + TB - 1) / TB;   // warp per node

    // --- CSR build: one cooperative kernel ---
    k_build<<<nb, TB>>>(X, src, dst, ew, nE, nb);

    // --- 3 pull layers (high-occupancy, fp16 gathers, fp32 accum + mean) ---
    k_pull_h<<<gridPull, TB>>>(hX, h1);                  // h1
    k_pull_h<<<gridPull, TB>>>(h1, h2);                  // h2
    k_pull_final_h<<<gridPull, TB>>>(h2, X, h1, out);    // h3 + mean
}